// round 2
// baseline (speedup 1.0000x reference)
#include <cuda_runtime.h>
#include <cuda_bf16.h>

// Problem constants (fixed by reference setup_inputs)
#define BB 1024
#define NN 4096
#define CC 21
#define NTHREADS 256

// Scratch (__device__ globals are the allowed scratch path)
__device__ float g_partials[BB];
__device__ int   g_is64;

// Detect whether the class-index buffer is int64 (little-endian: odd int32
// words are high halves == 0 since values < 21) or int32. Reads only the
// first 1024 int32 words, which is in-bounds for both layouts.
__global__ void detect_idx_kernel(const int* __restrict__ cls32) {
    int all_zero = 1;
    for (int i = 1 + (int)threadIdx.x * 2; i < BB; i += 64) {
        if (cls32[i] != 0) all_zero = 0;
    }
    // AND-reduce across warp
    all_zero = __all_sync(0xffffffffu, all_zero);
    if (threadIdx.x == 0) g_is64 = all_zero;
}

__device__ __forceinline__ float point_norm(float x, float y, float z,
                                            float c0, float c1, float c2,
                                            float c3, float c4, float c5) {
    // q = c0*x^2 + c1*y^2 + c2*z^2 + c3*x*y + c4*x*z + c5*y*z  (c3..c5 carry the 2x)
    float q = fmaf(x, fmaf(c0, x, fmaf(c3, y, c4 * z)),
               fmaf(y, fmaf(c1, y, c5 * z),
                    c2 * z * z));
    // sqrt(q) via q * rsqrt(q); guard q<=0 (rounding can give tiny negatives)
    return (q > 0.0f) ? q * __frsqrt_rn(q) : 0.0f;
}

__global__ void __launch_bounds__(NTHREADS)
point_loss_kernel(const float* __restrict__ pred_q,
                  const float* __restrict__ gt_q,
                  const void* __restrict__ cls_raw,
                  const float* __restrict__ bank) {
    const int b = blockIdx.x;
    const int tid = threadIdx.x;

    __shared__ float sc[6];
    __shared__ float swarp[NTHREADS / 32];

    if (tid == 0) {
        // Build R_pred, R_gt exactly per reference quaternion_to_matrix
        float Rp[9], Rg[9];
        {
            float x = pred_q[4 * b + 0], y = pred_q[4 * b + 1];
            float z = pred_q[4 * b + 2], w = pred_q[4 * b + 3];
            float x2 = x * x, y2 = y * y, z2 = z * z;
            float xy = x * y, xz = x * z, yz = y * z;
            float wx = w * x, wy = w * y, wz = w * z;
            Rp[0] = 1.0f - 2.0f * (y2 + z2); Rp[1] = 2.0f * (xy - wz); Rp[2] = 2.0f * (xz + wy);
            Rp[3] = 2.0f * (xy + wz); Rp[4] = 1.0f - 2.0f * (x2 + z2); Rp[5] = 2.0f * (yz - wx);
            Rp[6] = 2.0f * (xz - wy); Rp[7] = 2.0f * (yz + wx); Rp[8] = 1.0f - 2.0f * (x2 + y2);
        }
        {
            float x = gt_q[4 * b + 0], y = gt_q[4 * b + 1];
            float z = gt_q[4 * b + 2], w = gt_q[4 * b + 3];
            float x2 = x * x, y2 = y * y, z2 = z * z;
            float xy = x * y, xz = x * z, yz = y * z;
            float wx = w * x, wy = w * y, wz = w * z;
            Rg[0] = 1.0f - 2.0f * (y2 + z2); Rg[1] = 2.0f * (xy - wz); Rg[2] = 2.0f * (xz + wy);
            Rg[3] = 2.0f * (xy + wz); Rg[4] = 1.0f - 2.0f * (x2 + z2); Rg[5] = 2.0f * (yz - wx);
            Rg[6] = 2.0f * (xz - wy); Rg[7] = 2.0f * (yz + wx); Rg[8] = 1.0f - 2.0f * (x2 + y2);
        }
        float d[9];
        #pragma unroll
        for (int i = 0; i < 9; i++) d[i] = Rp[i] - Rg[i];

        // M = dR^T dR (symmetric). Column k of dR is d[k], d[k+3], d[k+6].
        float M00 = d[0]*d[0] + d[3]*d[3] + d[6]*d[6];
        float M11 = d[1]*d[1] + d[4]*d[4] + d[7]*d[7];
        float M22 = d[2]*d[2] + d[5]*d[5] + d[8]*d[8];
        float M01 = d[0]*d[1] + d[3]*d[4] + d[6]*d[7];
        float M02 = d[0]*d[2] + d[3]*d[5] + d[6]*d[8];
        float M12 = d[1]*d[2] + d[4]*d[5] + d[7]*d[8];
        sc[0] = M00; sc[1] = M11; sc[2] = M22;
        sc[3] = 2.0f * M01; sc[4] = 2.0f * M02; sc[5] = 2.0f * M12;
    }
    __syncthreads();

    const float c0 = sc[0], c1 = sc[1], c2 = sc[2];
    const float c3 = sc[3], c4 = sc[4], c5 = sc[5];

    // Class index: dtype-robust read + clamp (wrong guess -> rel_err, never a crash)
    int cidx;
    if (g_is64) cidx = (int)((const long long*)cls_raw)[b];
    else        cidx = ((const int*)cls_raw)[b];
    cidx = min(max(cidx, 0), CC - 1);

    const size_t cofs = (size_t)cidx * (size_t)(NN * 3);
    const float4* __restrict__ base4 = (const float4*)(bank + cofs);

    float acc = 0.0f;
    // 4096 points = 1024 "triples" of 3 float4 (= 4 points each)
    #pragma unroll
    for (int it = 0; it < (NN / 4) / NTHREADS; ++it) {
        int tri = it * NTHREADS + tid;
        float4 a = base4[tri * 3 + 0];
        float4 v = base4[tri * 3 + 1];
        float4 w = base4[tri * 3 + 2];
        acc += point_norm(a.x, a.y, a.z, c0, c1, c2, c3, c4, c5);
        acc += point_norm(a.w, v.x, v.y, c0, c1, c2, c3, c4, c5);
        acc += point_norm(v.z, v.w, w.x, c0, c1, c2, c3, c4, c5);
        acc += point_norm(w.y, w.z, w.w, c0, c1, c2, c3, c4, c5);
    }

    // Warp reduce
    #pragma unroll
    for (int o = 16; o > 0; o >>= 1)
        acc += __shfl_xor_sync(0xffffffffu, acc, o);
    if ((tid & 31) == 0) swarp[tid >> 5] = acc;
    __syncthreads();
    if (tid == 0) {
        float s = 0.0f;
        #pragma unroll
        for (int i = 0; i < NTHREADS / 32; i++) s += swarp[i];
        g_partials[b] = s;
    }
}

__global__ void __launch_bounds__(256)
reduce_kernel(float* __restrict__ out) {
    __shared__ double sm[256];
    int t = threadIdx.x;
    double s = (double)g_partials[t]
             + (double)g_partials[t + 256]
             + (double)g_partials[t + 512]
             + (double)g_partials[t + 768];
    sm[t] = s;
    __syncthreads();
    #pragma unroll
    for (int o = 128; o > 0; o >>= 1) {
        if (t < o) sm[t] += sm[t + o];
        __syncthreads();
    }
    if (t == 0) out[0] = (float)(sm[0] / (double)((long long)BB * NN));
}

extern "C" void kernel_launch(void* const* d_in, const int* in_sizes, int n_in,
                              void* d_out, int out_size) {
    // Resolve inputs by element count (robust to metadata ordering):
    //   pred_q / gt_q : 4096 elems (order of appearance; loss is symmetric in swap)
    //   class_indices : 1024 elems
    //   point_bank    : 258048 elems
    const float* pred_q = nullptr;
    const float* gt_q   = nullptr;
    const void*  cls    = nullptr;
    const float* bank   = nullptr;

    for (int i = 0; i < n_in; i++) {
        int sz = in_sizes[i];
        if (sz == BB) {
            cls = d_in[i];
        } else if (sz == CC * NN * 3) {
            bank = (const float*)d_in[i];
        } else if (sz == BB * 4) {
            if (!pred_q) pred_q = (const float*)d_in[i];
            else         gt_q   = (const float*)d_in[i];
        }
    }
    float* out = (float*)d_out;

    detect_idx_kernel<<<1, 32>>>((const int*)cls);
    point_loss_kernel<<<BB, NTHREADS>>>(pred_q, gt_q, cls, bank);
    reduce_kernel<<<1, 256>>>(out);
}